// round 16
// baseline (speedup 1.0000x reference)
#include <cuda_runtime.h>

#define Bz 8
#define Hn 4
#define Ln 256
#define Dn 32
#define NROWS (Bz * Hn * Ln)     // 8192
#define PGRID 592                // 148 SMs x 4 resident CTAs

__global__ __launch_bounds__(256, 4)
void taa_kernel(const float* __restrict__ Q, const float* __restrict__ K,
                const float* __restrict__ V, const float* __restrict__ tmK,
                const float* __restrict__ tmV, const float* __restrict__ amask,
                const unsigned char* __restrict__ pad,
                float* __restrict__ x_out, float* __restrict__ attn_out)
{
    __shared__ float sQ[Dn];
    __shared__ float sE[Ln];          // energy, then attn
    __shared__ float2 wms[8];         // per-warp (max, sum) pairs
    __shared__ float red[32 * Dn];    // 32 k0-groups x 32 d
    __shared__ float red2[8 * Dn];    // second-stage partials

    const int tid  = threadIdx.x;
    const int lane = tid & 31;
    const int wid  = tid >> 5;
    const int k0 = tid >> 3;      // 0..31
    const int dq = tid & 7;       // 0..7 (float4 index within D=32)

    // Persistent CTA: loop over rows, no wave transitions.
    for (int gq = blockIdx.x; gq < NROWS; gq += PGRID) {
        const int q  = gq & (Ln - 1);
        const int bh = gq >> 8;
        const int b  = bh >> 2;            // Hn = 4

        const float* __restrict__ tmKq = tmK + (size_t)gq * Ln * Dn;
        const float* __restrict__ tmVq = tmV + (size_t)gq * Ln * Dn;
        const float* __restrict__ Kbh  = K + (size_t)bh * Ln * Dn;
        const float* __restrict__ Vbh  = V + (size_t)bh * Ln * Dn;

        // Fold 1/sqrt(D) into Q once.
        if (tid < Dn) sQ[tid] = Q[(size_t)gq * Dn + tid] * 0.17677669529663689f;
        __syncthreads();

        const float4 q4 = reinterpret_cast<const float4*>(sQ)[dq];

        // ---------------- Phase 1: energy[k] = (tmK[k,:]+K[k,:]) . Qs ----------------
#pragma unroll
        for (int j = 0; j < 8; j++) {
            const int k = k0 + 32 * j;
            const float4 tk = __ldg(reinterpret_cast<const float4*>(tmKq + (size_t)k * Dn) + dq);
            const float4 kv = __ldg(reinterpret_cast<const float4*>(Kbh  + (size_t)k * Dn) + dq);
            float p = (tk.x + kv.x) * q4.x + (tk.y + kv.y) * q4.y
                    + (tk.z + kv.z) * q4.z + (tk.w + kv.w) * q4.w;
            p += __shfl_down_sync(0xffffffffu, p, 4, 8);
            p += __shfl_down_sync(0xffffffffu, p, 2, 8);
            p += __shfl_down_sync(0xffffffffu, p, 1, 8);
            if (dq == 0) sE[k] = p;
        }
        __syncthreads();

        // ---------------- Softmax: single-barrier online combine ----------------
        float e = sE[tid] + amask[q * Ln + tid];
        if (pad[b * Ln + tid]) e = -4294967295.0f;      // -2^32 + 1

        float mw = e;
#pragma unroll
        for (int o = 16; o > 0; o >>= 1) mw = fmaxf(mw, __shfl_xor_sync(0xffffffffu, mw, o));
        const float exl = __expf(e - mw);
        float sw = exl;
#pragma unroll
        for (int o = 16; o > 0; o >>= 1) sw += __shfl_xor_sync(0xffffffffu, sw, o);
        if (lane == 0) wms[wid] = make_float2(mw, sw);
        __syncthreads();

        float M = wms[0].x;
#pragma unroll
        for (int i = 1; i < 8; i++) M = fmaxf(M, wms[i].x);
        float S = 0.f;
#pragma unroll
        for (int i = 0; i < 8; i++) S += wms[i].y * __expf(wms[i].x - M);

        const float a = exl * __expf(mw - M) * __frcp_rn(S);
        sE[tid] = a;                  // sole prior reader was this thread
        attn_out[(size_t)gq * Ln + tid] = a;
        __syncthreads();

        // ---------------- Phase 2: x[d] = sum_k attn[k]*(tmV[k,d]+V[k,d]) ----------------
        float4 acc = make_float4(0.f, 0.f, 0.f, 0.f);
#pragma unroll
        for (int j = 0; j < 8; j++) {
            const int k = k0 + 32 * j;
            const float av = sE[k];
            const float4 tv = __ldg(reinterpret_cast<const float4*>(tmVq + (size_t)k * Dn) + dq);
            const float4 vv = __ldg(reinterpret_cast<const float4*>(Vbh  + (size_t)k * Dn) + dq);
            acc.x += av * (tv.x + vv.x);
            acc.y += av * (tv.y + vv.y);
            acc.z += av * (tv.z + vv.z);
            acc.w += av * (tv.w + vv.w);
        }
        reinterpret_cast<float4*>(red + k0 * Dn)[dq] = acc;
        __syncthreads();

        // Two-stage tail reduction using all 256 threads.
        {
            const int d  = tid & 31;
            const int g0 = tid >> 5;     // 0..7
            float ps = red[g0 * Dn + d] + red[(g0 + 8) * Dn + d]
                     + red[(g0 + 16) * Dn + d] + red[(g0 + 24) * Dn + d];
            red2[g0 * Dn + d] = ps;
        }
        __syncthreads();

        if (tid < Dn) {
            float xs = 0.f;
#pragma unroll
            for (int g = 0; g < 8; g++) xs += red2[g * Dn + tid];
            x_out[(size_t)gq * Dn + tid] = xs;
        }
        __syncthreads();   // protect smem (red2/sE/sQ) before next row
    }
}

extern "C" void kernel_launch(void* const* d_in, const int* in_sizes, int n_in,
                              void* d_out, int out_size)
{
    const float* Q    = (const float*)d_in[0];
    const float* K    = (const float*)d_in[1];
    const float* V    = (const float*)d_in[2];
    const float* tmK  = (const float*)d_in[3];
    const float* tmV  = (const float*)d_in[4];
    const float* mask = (const float*)d_in[5];
    const unsigned char* pad = (const unsigned char*)d_in[6];

    float* out  = (float*)d_out;
    float* x    = out;                                // [B,H,L,D]
    float* attn = out + (size_t)Bz * Hn * Ln * Dn;    // [B,H,L,L]

    taa_kernel<<<PGRID, 256>>>(Q, K, V, tmK, tmV, mask, pad, x, attn);
}

// round 17
// speedup vs baseline: 1.0801x; 1.0801x over previous
#include <cuda_runtime.h>

#define Bz 8
#define Hn 4
#define Ln 256
#define Dn 32

__global__ __launch_bounds__(256, 4)
void taa_kernel(const float* __restrict__ Q, const float* __restrict__ K,
                const float* __restrict__ V, const float* __restrict__ tmK,
                const float* __restrict__ tmV, const float* __restrict__ amask,
                const unsigned char* __restrict__ pad,
                float* __restrict__ x_out, float* __restrict__ attn_out)
{
    __shared__ float sQ[Dn];
    __shared__ float sE[Ln];          // energy, then attn
    __shared__ float2 wms[8];         // per-warp (max, sum) pairs
    __shared__ float red[32 * Dn];    // 32 k0-groups x 32 d
    __shared__ float red2[8 * Dn];    // second-stage partials

    const int bid = blockIdx.x;
    const int q = bid & (Ln - 1);
    const int h = (bid >> 8) & (Hn - 1);
    const int b = bid >> 10;

    const int tid  = threadIdx.x;
    const int lane = tid & 31;
    const int wid  = tid >> 5;

    const int bh = b * Hn + h;
    const float* __restrict__ Qrow = Q   + ((size_t)bh * Ln + q) * Dn;
    const float* __restrict__ tmKq = tmK + (((size_t)bh * Ln + q) * Ln) * Dn;
    const float* __restrict__ tmVq = tmV + (((size_t)bh * Ln + q) * Ln) * Dn;
    const float* __restrict__ Kbh  = K + (size_t)bh * Ln * Dn;
    const float* __restrict__ Vbh  = V + (size_t)bh * Ln * Dn;

    // Fold 1/sqrt(D) into Q once.
    if (tid < Dn) sQ[tid] = Qrow[tid] * 0.17677669529663689f;
    __syncthreads();

    const int k0 = tid >> 3;      // 0..31
    const int dq = tid & 7;       // 0..7 (float4 index within D=32)
    const float4 q4 = reinterpret_cast<const float4*>(sQ)[dq];

    // ---------------- Phase 1: energy[k] = (tmK[k,:]+K[k,:]) . Qs ----------------
#pragma unroll
    for (int j = 0; j < 8; j++) {
        const int k = k0 + 32 * j;
        const float4 tk = __ldg(reinterpret_cast<const float4*>(tmKq + (size_t)k * Dn) + dq);
        const float4 kv = __ldg(reinterpret_cast<const float4*>(Kbh  + (size_t)k * Dn) + dq);
        float p = (tk.x + kv.x) * q4.x + (tk.y + kv.y) * q4.y
                + (tk.z + kv.z) * q4.z + (tk.w + kv.w) * q4.w;
        p += __shfl_down_sync(0xffffffffu, p, 4, 8);
        p += __shfl_down_sync(0xffffffffu, p, 2, 8);
        p += __shfl_down_sync(0xffffffffu, p, 1, 8);
        if (dq == 0) sE[k] = p;
    }
    __syncthreads();

    // ---------------- Softmax: single-barrier online combine ----------------
    float e = sE[tid] + amask[q * Ln + tid];
    if (pad[b * Ln + tid]) e = -4294967295.0f;      // -2^32 + 1

    float mw = e;
#pragma unroll
    for (int o = 16; o > 0; o >>= 1) mw = fmaxf(mw, __shfl_xor_sync(0xffffffffu, mw, o));
    const float exl = __expf(e - mw);
    float sw = exl;
#pragma unroll
    for (int o = 16; o > 0; o >>= 1) sw += __shfl_xor_sync(0xffffffffu, sw, o);
    if (lane == 0) wms[wid] = make_float2(mw, sw);
    __syncthreads();

    float M = wms[0].x;
#pragma unroll
    for (int i = 1; i < 8; i++) M = fmaxf(M, wms[i].x);
    float S = 0.f;
#pragma unroll
    for (int i = 0; i < 8; i++) S += wms[i].y * __expf(wms[i].x - M);

    const float a = exl * __expf(mw - M) * __frcp_rn(S);
    sE[tid] = a;                  // sole prior reader was this thread
    attn_out[((size_t)bh * Ln + q) * Ln + tid] = a;
    __syncthreads();

    // ---------------- Phase 2: x[d] = sum_k attn[k]*(tmV[k,d]+V[k,d]) ----------------
    float4 acc = make_float4(0.f, 0.f, 0.f, 0.f);
#pragma unroll
    for (int j = 0; j < 8; j++) {
        const int k = k0 + 32 * j;
        const float av = sE[k];
        const float4 tv = __ldg(reinterpret_cast<const float4*>(tmVq + (size_t)k * Dn) + dq);
        const float4 vv = __ldg(reinterpret_cast<const float4*>(Vbh  + (size_t)k * Dn) + dq);
        acc.x += av * (tv.x + vv.x);
        acc.y += av * (tv.y + vv.y);
        acc.z += av * (tv.z + vv.z);
        acc.w += av * (tv.w + vv.w);
    }
    reinterpret_cast<float4*>(red + k0 * Dn)[dq] = acc;
    __syncthreads();

    // Two-stage tail reduction using all 256 threads.
    {
        const int d  = tid & 31;
        const int g0 = tid >> 5;     // 0..7
        float ps = red[g0 * Dn + d] + red[(g0 + 8) * Dn + d]
                 + red[(g0 + 16) * Dn + d] + red[(g0 + 24) * Dn + d];
        red2[g0 * Dn + d] = ps;
    }
    __syncthreads();

    if (tid < Dn) {
        float xs = 0.f;
#pragma unroll
        for (int g = 0; g < 8; g++) xs += red2[g * Dn + tid];
        x_out[((size_t)bh * Ln + q) * Dn + tid] = xs;
    }
}

extern "C" void kernel_launch(void* const* d_in, const int* in_sizes, int n_in,
                              void* d_out, int out_size)
{
    const float* Q    = (const float*)d_in[0];
    const float* K    = (const float*)d_in[1];
    const float* V    = (const float*)d_in[2];
    const float* tmK  = (const float*)d_in[3];
    const float* tmV  = (const float*)d_in[4];
    const float* mask = (const float*)d_in[5];
    const unsigned char* pad = (const unsigned char*)d_in[6];

    float* out  = (float*)d_out;
    float* x    = out;                                // [B,H,L,D]
    float* attn = out + (size_t)Bz * Hn * Ln * Dn;    // [B,H,L,L]

    taa_kernel<<<Bz * Hn * Ln, 256>>>(Q, K, V, tmK, tmV, mask, pad, x, attn);
}